// round 2
// baseline (speedup 1.0000x reference)
#include <cuda_runtime.h>
#include <cstddef>

// Problem constants
#define SQ   512      // sequence length S
#define ED   512      // embedding dim E
#define HD   512      // hidden dim H
#define G4   2048     // 4*H gates
#define BSEL 63       // only batch sample 63 reaches the output
#define NVOC 32000

#define NCTA 128
#define SCAN_THREADS 256

// Scratch (device globals; no allocation allowed)
__device__ unsigned long long g_hist[SQ * HD];   // {float h, uint tag} per element, 2 MB
__device__ float g_xg[SQ * G4];                  // precomputed input-gate projections, 4 MB
__device__ int g_tok[SQ];                        // batch-63 tokens, dtype-normalized

// ---------------------------------------------------------------------------
// Kernel 0a: zero the tag/history buffer so graph replays are deterministic.
// ---------------------------------------------------------------------------
__global__ void zero_hist_kernel() {
    int idx = blockIdx.x * blockDim.x + threadIdx.x;
    int stride = gridDim.x * blockDim.x;
    for (int i = idx; i < SQ * HD; i += stride) g_hist[i] = 0ULL;
}

// ---------------------------------------------------------------------------
// Kernel 0b: normalize token dtype (int32 vs int64) and extract batch 63.
// int64 tokens < 32000 => every odd 32-bit word is 0. int32 random tokens
// => some odd word is nonzero (P(all zero) ~ 32000^-256).
// ---------------------------------------------------------------------------
__global__ void __launch_bounds__(SQ) token_prep_kernel(const int* __restrict__ raw) {
    __shared__ int any_nz;
    const int tid = threadIdx.x;            // 0..511
    if (tid == 0) any_nz = 0;
    __syncthreads();
    if (tid < 256 && raw[2 * tid + 1] != 0) atomicExch(&any_nz, 1);
    __syncthreads();
    const bool is64 = (any_nz == 0);
    const long long idx = (long long)BSEL * SQ + tid;
    int tok = is64 ? raw[2 * idx] : raw[idx];
    tok = min(max(tok, 0), NVOC - 1);       // never IMA, even on dtype surprise
    g_tok[tid] = tok;
}

// ---------------------------------------------------------------------------
// Kernel 1: xg[s,g] = sum_e emb[tok_s, e] * W_ih[g, e] + b_ih[g] + b_hh[g]
// 512x2048x512 GEMM, smem-tiled SIMT (BM=64, BN=64, BK=16, 4x4/thread)
// ---------------------------------------------------------------------------
#define BM 64
#define BN 64
#define BK 16

__global__ void __launch_bounds__(256) xg_gemm_kernel(
    const float* __restrict__ emb,
    const float* __restrict__ Wih,
    const float* __restrict__ bih,
    const float* __restrict__ bhh)
{
    __shared__ float As[BK][BM];
    __shared__ float Bs[BK][BN];
    __shared__ int   toks[BM];

    const int bs = blockIdx.x * BM;   // s base
    const int bg = blockIdx.y * BN;   // g base
    const int tid = threadIdx.x;

    if (tid < BM) toks[tid] = g_tok[bs + tid];
    __syncthreads();

    const int tm = (tid >> 4) << 2;   // 0,4,...,60
    const int tn = (tid & 15) << 2;   // 0,4,...,60

    float acc[4][4];
    #pragma unroll
    for (int i = 0; i < 4; i++)
        #pragma unroll
        for (int j = 0; j < 4; j++) acc[i][j] = 0.f;

    for (int k0 = 0; k0 < ED; k0 += BK) {
        #pragma unroll
        for (int i = tid; i < BM * BK; i += 256) {
            int m = i >> 4, k = i & 15;
            As[k][m] = emb[(size_t)toks[m] * ED + k0 + k];
        }
        #pragma unroll
        for (int i = tid; i < BN * BK; i += 256) {
            int n = i >> 4, k = i & 15;
            Bs[k][n] = Wih[(size_t)(bg + n) * ED + k0 + k];
        }
        __syncthreads();
        #pragma unroll
        for (int k = 0; k < BK; k++) {
            float4 a = *(const float4*)&As[k][tm];
            float4 b = *(const float4*)&Bs[k][tn];
            float av[4] = {a.x, a.y, a.z, a.w};
            float bv[4] = {b.x, b.y, b.z, b.w};
            #pragma unroll
            for (int i = 0; i < 4; i++)
                #pragma unroll
                for (int j = 0; j < 4; j++)
                    acc[i][j] = fmaf(av[i], bv[j], acc[i][j]);
        }
        __syncthreads();
    }

    #pragma unroll
    for (int i = 0; i < 4; i++) {
        int s = bs + tm + i;
        #pragma unroll
        for (int j = 0; j < 4; j++) {
            int g = bg + tn + j;
            g_xg[(size_t)s * G4 + g] = acc[i][j] + bih[g] + bhh[g];
        }
    }
}

// ---------------------------------------------------------------------------
// Kernel 2: persistent LSTM scan, batch element 63 only.
// 128 CTAs, each owns 4 hidden indices (16 gate rows of W_hh in registers).
// Cross-SM h broadcast via tagged 8-byte words in g_hist (ld.volatile polling).
// ---------------------------------------------------------------------------
__device__ __forceinline__ float sigmoidf_(float x) {
    return 1.f / (1.f + __expf(-x));
}
__device__ __forceinline__ float tanhf_(float x) {
    x = fminf(fmaxf(x, -15.f), 15.f);
    float e = __expf(2.f * x);
    return (e - 1.f) / (e + 1.f);
}

__global__ void __launch_bounds__(SCAN_THREADS, 1) lstm_scan_kernel(
    const float* __restrict__ h0,
    const float* __restrict__ c0,
    const float* __restrict__ Whh)
{
    __shared__ float xg_s[SQ * 16];   // this CTA's 16 gate columns, all 512 steps (32 KB)
    __shared__ float h_sm[HD];        // current h (staged once per step per CTA)
    __shared__ float gexch[16];       // gate pre-activations exchange

    const int cta = blockIdx.x;       // 0..127, owns h indices [cta*4, cta*4+4)
    const int tid = threadIdx.x;
    const int w = tid >> 5;           // warp 0..7
    const int l = tid & 31;

    // Preload xg slice: local gate lg in [0,16): group = lg>>2 (i,f,g,o), j = lg&3
    for (int i = tid; i < SQ * 16; i += SCAN_THREADS) {
        int s = i >> 4, lg = i & 15;
        int g = ((lg >> 2) << 9) + (cta << 2) + (lg & 3);
        xg_s[i] = g_xg[((size_t)s << 11) + g];
    }

    // Each warp owns local gates 2w, 2w+1; weights into registers (32 regs/thread)
    const int lg0 = 2 * w, lg1 = 2 * w + 1;
    const int r0 = ((lg0 >> 2) << 9) + (cta << 2) + (lg0 & 3);
    const int r1 = ((lg1 >> 2) << 9) + (cta << 2) + (lg1 & 3);
    float wt0[16], wt1[16];
    #pragma unroll
    for (int k = 0; k < 4; k++) {
        float4 v = *(const float4*)&Whh[(size_t)r0 * HD + (l << 2) + (k << 7)];
        wt0[k * 4 + 0] = v.x; wt0[k * 4 + 1] = v.y; wt0[k * 4 + 2] = v.z; wt0[k * 4 + 3] = v.w;
        float4 u = *(const float4*)&Whh[(size_t)r1 * HD + (l << 2) + (k << 7)];
        wt1[k * 4 + 0] = u.x; wt1[k * 4 + 1] = u.y; wt1[k * 4 + 2] = u.z; wt1[k * 4 + 3] = u.w;
    }

    float creg = 0.f;
    if (w == 0 && l < 4) creg = c0[(size_t)BSEL * HD + (cta << 2) + l];

    // Seed h_sm with h0[0, 63, :]
    for (int i = tid; i < HD; i += SCAN_THREADS) h_sm[i] = h0[(size_t)BSEL * HD + i];
    __syncthreads();

    for (int t = 0; t < SQ; t++) {
        if (t > 0) {
            // Each warp polls its disjoint 64-element chunk of h(t-1), 2 per lane.
            const unsigned long long* p = g_hist + ((size_t)(t - 1) << 9) + (w << 6) + (l << 1);
            unsigned long long a, b;
            const unsigned want = (unsigned)t;
            for (;;) {
                asm volatile("ld.volatile.global.v2.u64 {%0,%1}, [%2];"
                             : "=l"(a), "=l"(b) : "l"(p));
                bool ok = ((unsigned)(a >> 32) == want) && ((unsigned)(b >> 32) == want);
                if (__all_sync(0xffffffffu, ok)) break;
            }
            const int e0 = (w << 6) + (l << 1);
            h_sm[e0]     = __uint_as_float((unsigned)a);
            h_sm[e0 + 1] = __uint_as_float((unsigned)b);
            __syncthreads();
        }

        // Two 512-length dot products per warp (h from smem, W from registers)
        float hreg[16];
        #pragma unroll
        for (int k = 0; k < 4; k++) {
            float4 v = *(const float4*)&h_sm[(l << 2) + (k << 7)];
            hreg[k * 4 + 0] = v.x; hreg[k * 4 + 1] = v.y;
            hreg[k * 4 + 2] = v.z; hreg[k * 4 + 3] = v.w;
        }
        float d0 = 0.f, d1 = 0.f;
        #pragma unroll
        for (int i = 0; i < 16; i++) {
            d0 = fmaf(wt0[i], hreg[i], d0);
            d1 = fmaf(wt1[i], hreg[i], d1);
        }
        #pragma unroll
        for (int off = 16; off; off >>= 1) {
            d0 += __shfl_xor_sync(0xffffffffu, d0, off);
            d1 += __shfl_xor_sync(0xffffffffu, d1, off);
        }
        if (l == 0) {
            gexch[lg0] = d0 + xg_s[(t << 4) + lg0];
            gexch[lg1] = d1 + xg_s[(t << 4) + lg1];
        }
        __syncthreads();

        // Warp 0 lanes 0..3: activations + state update + tagged publish
        if (w == 0 && l < 4) {
            float iv = sigmoidf_(gexch[l]);
            float fv = sigmoidf_(gexch[4 + l]);
            float gv = tanhf_(gexch[8 + l]);
            float ov = sigmoidf_(gexch[12 + l]);
            creg = fv * creg + iv * gv;
            float hv = ov * tanhf_(creg);
            unsigned long long pk =
                ((unsigned long long)(unsigned)(t + 1) << 32) |
                (unsigned long long)__float_as_uint(hv);
            unsigned long long* dst = g_hist + ((size_t)t << 9) + (cta << 2) + l;
            asm volatile("st.volatile.global.u64 [%0], %1;" :: "l"(dst), "l"(pk) : "memory");
        }
        // No trailing syncthreads needed: next iteration's h_sm writes only race
        // with reads that already completed before the gexch barrier.
    }
}

// ---------------------------------------------------------------------------
// Kernel 3: out[s,t] = hist[s,:] . W_lin[t,:] + b_lin[t]   (1024 outputs)
// ---------------------------------------------------------------------------
__global__ void __launch_bounds__(256) final_linear_kernel(
    const float* __restrict__ Wlin,
    const float* __restrict__ blin,
    float* __restrict__ out)
{
    const int w = threadIdx.x >> 5, l = threadIdx.x & 31;
    const int wi = blockIdx.x * 8 + w;     // 0..1023
    const int s = wi >> 1, tt = wi & 1;
    float acc = 0.f;
    #pragma unroll
    for (int e = l; e < HD; e += 32) {
        float hv = __uint_as_float((unsigned)g_hist[(size_t)s * HD + e]);
        acc = fmaf(hv, Wlin[(size_t)tt * HD + e], acc);
    }
    #pragma unroll
    for (int off = 16; off; off >>= 1) acc += __shfl_xor_sync(0xffffffffu, acc, off);
    if (l == 0) out[s * 2 + tt] = acc + blin[tt];
}

// ---------------------------------------------------------------------------
extern "C" void kernel_launch(void* const* d_in, const int* in_sizes, int n_in,
                              void* d_out, int out_size)
{
    const int*   sent = (const int*)d_in[0];            // (64,512) int32 (or int64 words)
    const float* h0   = (const float*)d_in[1];          // (1,64,512)
    const float* c0   = (const float*)d_in[2];          // (1,64,512)
    const float* emb  = (const float*)d_in[3];          // (32000,512)
    const float* Wih  = (const float*)d_in[4];          // (2048,512)
    const float* Whh  = (const float*)d_in[5];          // (2048,512)
    const float* bih  = (const float*)d_in[6];          // (2048,)
    const float* bhh  = (const float*)d_in[7];          // (2048,)
    const float* Wlin = (const float*)d_in[8];          // (2,512)
    const float* blin = (const float*)d_in[9];          // (2,)
    float* out = (float*)d_out;                         // (512,2)

    zero_hist_kernel<<<256, 256>>>();
    token_prep_kernel<<<1, SQ>>>(sent);
    xg_gemm_kernel<<<dim3(SQ / BM, G4 / BN), 256>>>(emb, Wih, bih, bhh);
    lstm_scan_kernel<<<NCTA, SCAN_THREADS>>>(h0, c0, Whh);
    final_linear_kernel<<<128, 256>>>(Wlin, blin, out);
}